// round 10
// baseline (speedup 1.0000x reference)
#include <cuda_runtime.h>
#include <cstring>

// out[m,o] = sum_c |x[m,c] - w[c,o]| + b[o]
//          = 2*sum_c max(x[m,c], w[c,o]) - Sx[m] - Sw[o] + b[o]
// R8's low-slot loop (broadcast x LDS.128, conflict-free w LDS.128, packed
// add.rn.f32x2) at R9-class residency: BM=32/BO=128 -> grid 784, 4m x 4o
// thread tile, regs capped for 5 blocks/SM (40 warps, ~62% occ).

constexpr int C    = 64;    // channels (reduction dim)
constexpr int CP   = 32;    // channels per split-K pass
constexpr int OUTC = 128;   // output channels
constexpr int BM   = 32;    // rows per block
constexpr int XS   = 36;    // padded stride for transposed x tile (32 + 4)

__device__ __forceinline__ void fadd2(unsigned long long& acc, float a, float b) {
    float2 t = make_float2(a, b);
    unsigned long long tv;
    memcpy(&tv, &t, 8);                 // PTX-visible pack -> ptxas coalesces (no MOVs, verified R8)
    asm("add.rn.f32x2 %0, %0, %1;" : "+l"(acc) : "l"(tv));
}

__global__ __launch_bounds__(256, 5)
void lp1_maxtrick_kernel(const float* __restrict__ x,
                         const float* __restrict__ w,
                         const float* __restrict__ b,
                         float* __restrict__ out)
{
    __shared__ float w_s[CP * OUTC];  // [c][o]  16 KB per pass
    __shared__ float x_s[CP * XS];    // [c][m]  4.6 KB per pass (transposed)
    __shared__ float sx_s[BM];
    __shared__ float beta_s[OUTC];

    const int tid   = threadIdx.x;
    const int m_blk = blockIdx.x * BM;

    const int o0 = (tid & 31) * 4;    // 32 o-groups over 128; 16B lane stride (conflict-free)
    const int m0 = (tid >> 5) * 4;    // warp-uniform -> broadcast x LDS.128

    unsigned long long acc[4][2];     // acc[i][k]: packed sums for o pair (2k, 2k+1)
    #pragma unroll
    for (int i = 0; i < 4; ++i) { acc[i][0] = 0ull; acc[i][1] = 0ull; }

    float beta_acc = (tid < OUTC) ? b[tid] : 0.f;   // -> b[o] - Sw[o]
    float sx_acc   = 0.f;                           // -> Sx[m]

    #pragma unroll
    for (int pass = 0; pass < 2; ++pass) {
        const int cbase = pass * CP;

        // ---- stage w half [CP][OUTC]: 1024 float4 (coalesced) ----
        #pragma unroll
        for (int i = 0; i < 4; ++i) {
            int idx = tid + 256 * i;              // 0..1023
            int c   = idx >> 5;                   // 32 float4 per c-row
            int o4  = idx & 31;
            *(float4*)(&w_s[c * OUTC + o4 * 4]) =
                *(const float4*)(w + (cbase + c) * OUTC + o4 * 4);
        }

        // ---- stage x half transposed: 256 float4 (first 256 threads) ----
        {
            int idx = tid;                        // 0..255
            int m   = idx >> 3;                   // 8 float4 per row (CP=32)
            int c   = (idx & 7) << 2;
            float4 v = *(const float4*)(x + (size_t)(m_blk + m) * C + cbase + c);
            x_s[(c + 0) * XS + m] = v.x;
            x_s[(c + 1) * XS + m] = v.y;
            x_s[(c + 2) * XS + m] = v.z;
            x_s[(c + 3) * XS + m] = v.w;
        }
        __syncthreads();

        // ---- prologue partials ----
        if (tid < OUTC) {
            #pragma unroll
            for (int c = 0; c < CP; ++c) beta_acc -= w_s[c * OUTC + tid];
        } else if (tid < OUTC + BM) {
            int m = tid - OUTC;
            #pragma unroll
            for (int c = 0; c < CP; ++c) sx_acc += x_s[c * XS + m];
        }

        // ---- main loop: 4m x 4o, 2 LDS.128 feed 16 warp-MACs ----
        #pragma unroll 16
        for (int c = 0; c < CP; ++c) {
            float4 xv = *(const float4*)(&x_s[c * XS + m0]);     // broadcast (1 wf)
            float4 wv = *(const float4*)(&w_s[c * OUTC + o0]);   // 16B stride (4 wf)
            float xa[4] = {xv.x, xv.y, xv.z, xv.w};
            #pragma unroll
            for (int i = 0; i < 4; ++i) {
                fadd2(acc[i][0], fmaxf(xa[i], wv.x), fmaxf(xa[i], wv.y));
                fadd2(acc[i][1], fmaxf(xa[i], wv.z), fmaxf(xa[i], wv.w));
            }
        }
        __syncthreads();   // protect restage of next pass
    }

    // ---- publish corrections ----
    if (tid < OUTC)            beta_s[tid]        = beta_acc;
    else if (tid < OUTC + BM)  sx_s[tid - OUTC]   = sx_acc;
    __syncthreads();

    // ---- epilogue: out = 2*acc - sx + beta ----
    float bet[4];
    #pragma unroll
    for (int j = 0; j < 4; ++j) bet[j] = beta_s[o0 + j];

    #pragma unroll
    for (int i = 0; i < 4; ++i) {
        float base = -sx_s[m0 + i];
        float2 p0, p1;
        memcpy(&p0, &acc[i][0], 8);
        memcpy(&p1, &acc[i][1], 8);
        float4 r;
        r.x = fmaf(2.f, p0.x, base + bet[0]);
        r.y = fmaf(2.f, p0.y, base + bet[1]);
        r.z = fmaf(2.f, p1.x, base + bet[2]);
        r.w = fmaf(2.f, p1.y, base + bet[3]);
        *(float4*)(out + (size_t)(m_blk + m0 + i) * OUTC + o0) = r;
    }
}

extern "C" void kernel_launch(void* const* d_in, const int* in_sizes, int n_in,
                              void* d_out, int out_size)
{
    const float* x = (const float*)d_in[0];   // [M, 64]
    const float* w = (const float*)d_in[1];   // [64, 128]
    const float* b = (const float*)d_in[2];   // [128]
    float* out = (float*)d_out;               // [M, 128]

    int M = in_sizes[0] / C;                  // 25088
    dim3 grid(M / BM, 1);                     // (784, 1)
    lp1_maxtrick_kernel<<<grid, 256>>>(x, w, b, out);
}

// round 12
// speedup vs baseline: 1.0875x; 1.0875x over previous
#include <cuda_runtime.h>
#include <cstring>

// out[m,o] = sum_c |x[m,c] - w[c,o]| + b[o]
// PIPE-SPLIT: channels 0..31 via max-trick (FMNMX on alu pipe + packed add on
// fma pipe); channels 32..63 via direct acc += |x-w| (2 FADD, pure fma pipe).
// Hypothesis: FMNMX is effectively half-rate on sm_103a (all 10 prior rounds
// pinned at cycles == FMNMX_count / 1-per-cycle); offloading half the MACs to
// the fma pipe should halve the wall. Frame identical to R10 (23.2us).

constexpr int C    = 64;    // channels
constexpr int CP   = 32;    // channels per pass (pass0 = max-trick, pass1 = abs)
constexpr int OUTC = 128;   // output channels
constexpr int BM   = 32;    // rows per block
constexpr int XS   = 36;    // padded stride for transposed x tile

__device__ __forceinline__ void fadd2(unsigned long long& acc, float a, float b) {
    float2 t = make_float2(a, b);
    unsigned long long tv;
    memcpy(&tv, &t, 8);                 // PTX-visible pack, coalesced by ptxas (R8-verified)
    asm("add.rn.f32x2 %0, %0, %1;" : "+l"(acc) : "l"(tv));
}

__global__ __launch_bounds__(256, 4)
void lp1_maxtrick_kernel(const float* __restrict__ x,
                         const float* __restrict__ w,
                         const float* __restrict__ b,
                         float* __restrict__ out)
{
    __shared__ float w_s[CP * OUTC];  // [c][o]  16 KB per pass
    __shared__ float x_s[CP * XS];    // [c][m]  4.6 KB per pass (transposed)
    __shared__ float sx_s[BM];
    __shared__ float beta_s[OUTC];

    const int tid   = threadIdx.x;
    const int m_blk = blockIdx.x * BM;

    const int o0 = (tid & 31) * 4;    // 32 o-groups over 128; 16B lane stride (conflict-free)
    const int m0 = (tid >> 5) * 4;    // warp-uniform -> broadcast x LDS.128

    unsigned long long acc2[4][2];    // pass0: packed max-sums, o pairs (2k,2k+1)
    float accf[4][4];                 // pass1: scalar |diff| sums
    #pragma unroll
    for (int i = 0; i < 4; ++i) {
        acc2[i][0] = 0ull; acc2[i][1] = 0ull;
        #pragma unroll
        for (int j = 0; j < 4; ++j) accf[i][j] = 0.f;
    }

    float beta_acc = (tid < OUTC) ? b[tid] : 0.f;   // -> b[o] - Sw[o] (pass0 channels only)
    float sx_acc   = 0.f;                           // -> Sx[m]        (pass0 channels only)

    #pragma unroll
    for (int pass = 0; pass < 2; ++pass) {
        const int cbase = pass * CP;

        // ---- stage w half [CP][OUTC]: 1024 float4 (coalesced) ----
        #pragma unroll
        for (int i = 0; i < 4; ++i) {
            int idx = tid + 256 * i;              // 0..1023
            int c   = idx >> 5;                   // 32 float4 per c-row
            int o4  = idx & 31;
            *(float4*)(&w_s[c * OUTC + o4 * 4]) =
                *(const float4*)(w + (cbase + c) * OUTC + o4 * 4);
        }

        // ---- stage x half transposed: 256 float4 ----
        {
            int idx = tid;                        // 0..255
            int m   = idx >> 3;                   // 8 float4 per row (CP=32)
            int c   = (idx & 7) << 2;
            float4 v = *(const float4*)(x + (size_t)(m_blk + m) * C + cbase + c);
            x_s[(c + 0) * XS + m] = v.x;
            x_s[(c + 1) * XS + m] = v.y;
            x_s[(c + 2) * XS + m] = v.z;
            x_s[(c + 3) * XS + m] = v.w;
        }
        __syncthreads();

        if (pass == 0) {
            // corrections cover ONLY the max-trick channels (c < 32)
            if (tid < OUTC) {
                #pragma unroll
                for (int c = 0; c < CP; ++c) beta_acc -= w_s[c * OUTC + tid];
            } else if (tid < OUTC + BM) {
                int m = tid - OUTC;
                #pragma unroll
                for (int c = 0; c < CP; ++c) sx_acc += x_s[c * XS + m];
            }

            // ---- pass0: max-trick (FMNMX on alu, packed add on fma) ----
            #pragma unroll 16
            for (int c = 0; c < CP; ++c) {
                float4 xv = *(const float4*)(&x_s[c * XS + m0]);     // broadcast
                float4 wv = *(const float4*)(&w_s[c * OUTC + o0]);   // 16B stride
                float xa[4] = {xv.x, xv.y, xv.z, xv.w};
                #pragma unroll
                for (int i = 0; i < 4; ++i) {
                    fadd2(acc2[i][0], fmaxf(xa[i], wv.x), fmaxf(xa[i], wv.y));
                    fadd2(acc2[i][1], fmaxf(xa[i], wv.z), fmaxf(xa[i], wv.w));
                }
            }
        } else {
            // ---- pass1: direct abs path (2 FADD per MAC, pure fma pipe) ----
            #pragma unroll 16
            for (int c = 0; c < CP; ++c) {
                float4 xv = *(const float4*)(&x_s[c * XS + m0]);     // broadcast
                float4 wv = *(const float4*)(&w_s[c * OUTC + o0]);   // 16B stride
                float xa[4] = {xv.x, xv.y, xv.z, xv.w};
                float wa[4] = {wv.x, wv.y, wv.z, wv.w};
                #pragma unroll
                for (int i = 0; i < 4; ++i)
                    #pragma unroll
                    for (int j = 0; j < 4; ++j)
                        accf[i][j] += fabsf(xa[i] - wa[j]);   // FADD + FADD(|src|)
            }
        }
        __syncthreads();   // protect restage of next pass
    }

    // ---- publish corrections ----
    if (tid < OUTC)            beta_s[tid]        = beta_acc;
    else if (tid < OUTC + BM)  sx_s[tid - OUTC]   = sx_acc;
    __syncthreads();

    // ---- epilogue: out = 2*Smax + Sabs - sx + beta ----
    float bet[4];
    #pragma unroll
    for (int j = 0; j < 4; ++j) bet[j] = beta_s[o0 + j];

    #pragma unroll
    for (int i = 0; i < 4; ++i) {
        float base = -sx_s[m0 + i];
        float2 p0, p1;
        memcpy(&p0, &acc2[i][0], 8);
        memcpy(&p1, &acc2[i][1], 8);
        float4 r;
        r.x = fmaf(2.f, p0.x, accf[i][0] + base + bet[0]);
        r.y = fmaf(2.f, p0.y, accf[i][1] + base + bet[1]);
        r.z = fmaf(2.f, p1.x, accf[i][2] + base + bet[2]);
        r.w = fmaf(2.f, p1.y, accf[i][3] + base + bet[3]);
        *(float4*)(out + (size_t)(m_blk + m0 + i) * OUTC + o0) = r;
    }
}

extern "C" void kernel_launch(void* const* d_in, const int* in_sizes, int n_in,
                              void* d_out, int out_size)
{
    const float* x = (const float*)d_in[0];   // [M, 64]
    const float* w = (const float*)d_in[1];   // [64, 128]
    const float* b = (const float*)d_in[2];   // [128]
    float* out = (float*)d_out;               // [M, 128]

    int M = in_sizes[0] / C;                  // 25088
    dim3 grid(M / BM, 1);                     // (784, 1)
    lp1_maxtrick_kernel<<<grid, 256>>>(x, w, b, out);
}

// round 13
// speedup vs baseline: 1.0890x; 1.0014x over previous
#include <cuda_runtime.h>
#include <cstring>

// out[m,o] = sum_c |x[m,c] - w[c,o]| + b[o]
// R12 frame (pipe-split: c<32 max-trick on alu, c>=32 direct |x-w| on fma;
// BM=32, BO=128, grid 784) + NEW: distance-2 software-pipelined LDS operands
// (ping-pong registers) so the L1tex-queue-inflated LDS latency is covered by
// ILP instead of (insufficient) TLP.

constexpr int C    = 64;
constexpr int CP   = 32;    // channels per pass (pass0 = max-trick, pass1 = abs)
constexpr int OUTC = 128;
constexpr int BM   = 32;
constexpr int XS   = 36;    // padded stride for transposed x tile

__device__ __forceinline__ void fadd2(unsigned long long& acc, float a, float b) {
    float2 t = make_float2(a, b);
    unsigned long long tv;
    memcpy(&tv, &t, 8);
    asm("add.rn.f32x2 %0, %0, %1;" : "+l"(acc) : "l"(tv));
}

__global__ __launch_bounds__(256)
void lp1_maxtrick_kernel(const float* __restrict__ x,
                         const float* __restrict__ w,
                         const float* __restrict__ b,
                         float* __restrict__ out)
{
    __shared__ float w_s[CP * OUTC];  // 16 KB per pass
    __shared__ float x_s[CP * XS];    // 4.6 KB per pass
    __shared__ float sx_s[BM];
    __shared__ float beta_s[OUTC];

    const int tid   = threadIdx.x;
    const int m_blk = blockIdx.x * BM;

    const int o0 = (tid & 31) * 4;    // 16B lane stride (conflict-free)
    const int m0 = (tid >> 5) * 4;    // warp-uniform -> broadcast x LDS.128

    unsigned long long acc2[4][2];    // pass0 packed max-sums
    float accf[4][4];                 // pass1 |diff| sums
    #pragma unroll
    for (int i = 0; i < 4; ++i) {
        acc2[i][0] = 0ull; acc2[i][1] = 0ull;
        #pragma unroll
        for (int j = 0; j < 4; ++j) accf[i][j] = 0.f;
    }

    float beta_acc = (tid < OUTC) ? b[tid] : 0.f;
    float sx_acc   = 0.f;

    #pragma unroll
    for (int pass = 0; pass < 2; ++pass) {
        const int cbase = pass * CP;

        // ---- stage w half [CP][OUTC] ----
        #pragma unroll
        for (int i = 0; i < 4; ++i) {
            int idx = tid + 256 * i;
            int c   = idx >> 5;
            int o4  = idx & 31;
            *(float4*)(&w_s[c * OUTC + o4 * 4]) =
                *(const float4*)(w + (cbase + c) * OUTC + o4 * 4);
        }
        // ---- stage x half transposed ----
        {
            int m = tid >> 3;
            int c = (tid & 7) << 2;
            float4 v = *(const float4*)(x + (size_t)(m_blk + m) * C + cbase + c);
            x_s[(c + 0) * XS + m] = v.x;
            x_s[(c + 1) * XS + m] = v.y;
            x_s[(c + 2) * XS + m] = v.z;
            x_s[(c + 3) * XS + m] = v.w;
        }
        __syncthreads();

        if (pass == 0) {
            if (tid < OUTC) {
                #pragma unroll
                for (int c = 0; c < CP; ++c) beta_acc -= w_s[c * OUTC + tid];
            } else if (tid < OUTC + BM) {
                int m = tid - OUTC;
                #pragma unroll
                for (int c = 0; c < CP; ++c) sx_acc += x_s[c * XS + m];
            }

            // ---- pass0: max-trick, distance-2 pipelined operands ----
            float4 xb[2], wb[2];
            xb[0] = *(const float4*)(&x_s[m0]);
            wb[0] = *(const float4*)(&w_s[o0]);
            xb[1] = *(const float4*)(&x_s[XS + m0]);
            wb[1] = *(const float4*)(&w_s[OUTC + o0]);
            #pragma unroll
            for (int c = 0; c < CP; ++c) {
                float4 xn = xb[c & 1], wn = wb[c & 1];
                if (c + 2 < CP) {                       // load 2 iters ahead
                    xb[c & 1] = *(const float4*)(&x_s[(c + 2) * XS + m0]);
                    wb[c & 1] = *(const float4*)(&w_s[(c + 2) * OUTC + o0]);
                }
                float xa[4] = {xn.x, xn.y, xn.z, xn.w};
                #pragma unroll
                for (int i = 0; i < 4; ++i) {
                    fadd2(acc2[i][0], fmaxf(xa[i], wn.x), fmaxf(xa[i], wn.y));
                    fadd2(acc2[i][1], fmaxf(xa[i], wn.z), fmaxf(xa[i], wn.w));
                }
            }
        } else {
            // ---- pass1: direct abs, distance-2 pipelined operands ----
            float4 xb[2], wb[2];
            xb[0] = *(const float4*)(&x_s[m0]);
            wb[0] = *(const float4*)(&w_s[o0]);
            xb[1] = *(const float4*)(&x_s[XS + m0]);
            wb[1] = *(const float4*)(&w_s[OUTC + o0]);
            #pragma unroll
            for (int c = 0; c < CP; ++c) {
                float4 xn = xb[c & 1], wn = wb[c & 1];
                if (c + 2 < CP) {
                    xb[c & 1] = *(const float4*)(&x_s[(c + 2) * XS + m0]);
                    wb[c & 1] = *(const float4*)(&w_s[(c + 2) * OUTC + o0]);
                }
                float xa[4] = {xn.x, xn.y, xn.z, xn.w};
                float wa[4] = {wn.x, wn.y, wn.z, wn.w};
                #pragma unroll
                for (int i = 0; i < 4; ++i)
                    #pragma unroll
                    for (int j = 0; j < 4; ++j)
                        accf[i][j] += fabsf(xa[i] - wa[j]);   // 2 FADD (fma pipe)
            }
        }
        __syncthreads();
    }

    // ---- publish corrections ----
    if (tid < OUTC)            beta_s[tid]      = beta_acc;
    else if (tid < OUTC + BM)  sx_s[tid - OUTC] = sx_acc;
    __syncthreads();

    // ---- epilogue: out = 2*Smax + Sabs - sx + beta ----
    float bet[4];
    #pragma unroll
    for (int j = 0; j < 4; ++j) bet[j] = beta_s[o0 + j];

    #pragma unroll
    for (int i = 0; i < 4; ++i) {
        float base = -sx_s[m0 + i];
        float2 p0, p1;
        memcpy(&p0, &acc2[i][0], 8);
        memcpy(&p1, &acc2[i][1], 8);
        float4 r;
        r.x = fmaf(2.f, p0.x, accf[i][0] + base + bet[0]);
        r.y = fmaf(2.f, p0.y, accf[i][1] + base + bet[1]);
        r.z = fmaf(2.f, p1.x, accf[i][2] + base + bet[2]);
        r.w = fmaf(2.f, p1.y, accf[i][3] + base + bet[3]);
        *(float4*)(out + (size_t)(m_blk + m0 + i) * OUTC + o0) = r;
    }
}

extern "C" void kernel_launch(void* const* d_in, const int* in_sizes, int n_in,
                              void* d_out, int out_size)
{
    const float* x = (const float*)d_in[0];   // [M, 64]
    const float* w = (const float*)d_in[1];   // [64, 128]
    const float* b = (const float*)d_in[2];   // [128]
    float* out = (float*)d_out;               // [M, 128]

    int M = in_sizes[0] / C;                  // 25088
    dim3 grid(M / BM, 1);                     // (784, 1)
    lp1_maxtrick_kernel<<<grid, 256>>>(x, w, b, out);
}